// round 1
// baseline (speedup 1.0000x reference)
#include <cuda_runtime.h>
#include <cstdint>

#define N_POS 2048
#define C_IN  256
#define C_OUT 256
#define BATCH 64
#define KC    32          // K-chunk per smem stage
#define NCHUNK (C_IN / KC)
#define PAD   33          // ws row stride (conflict-free: 8*33 % 32 = 8)

__device__ __forceinline__ unsigned long long pack2(float a, float b) {
    unsigned long long r;
    asm("mov.b64 %0, {%1, %2};" : "=l"(r) : "f"(a), "f"(b));
    return r;
}
__device__ __forceinline__ void unpack2(unsigned long long v, float& a, float& b) {
    asm("mov.b64 {%0, %1}, %2;" : "=f"(a), "=f"(b) : "l"(v));
}
__device__ __forceinline__ unsigned long long ffma2(unsigned long long a,
                                                    unsigned long long b,
                                                    unsigned long long c) {
    unsigned long long d;
    asm("fma.rn.f32x2 %0, %1, %2, %3;" : "=l"(d) : "l"(a), "l"(b), "l"(c));
    return d;
}

// One CTA per position i. 256 threads.
// Thread (og = tid/8, bg = tid%8) computes out tile o in [og*8, og*8+8), b in [bg*8, bg*8+8).
__global__ __launch_bounds__(256)
void fclayer_kernel(const float* __restrict__ x,     // [B, C_IN, N_POS]
                    const float* __restrict__ W,     // [N_POS, C_OUT, C_IN]
                    const float* __restrict__ bias,  // [N_POS, C_OUT]
                    float* __restrict__ out)         // [B, C_OUT, N_POS]
{
    __shared__ __align__(16) float ws[C_OUT * PAD];   // W chunk, [o][k] padded
    __shared__ __align__(16) float xs[KC * BATCH];    // x chunk, [k][b]

    const int i   = blockIdx.x;
    const int tid = threadIdx.x;
    const int bg  = tid & 7;
    const int og  = tid >> 3;
    const int o0  = og * 8;
    const int b0  = bg * 8;

    const float* Wi = W + (size_t)i * (C_OUT * C_IN);
    const float* xi = x + i;          // xi[(b*C_IN + c) * N_POS]
    float*       oi = out + i;        // oi[(b*C_OUT + o) * N_POS]

    // Accumulators: 8 o-rows x 4 b-pairs, initialized with bias (same per o across b).
    unsigned long long acc[8][4];
#pragma unroll
    for (int r = 0; r < 8; ++r) {
        float bv = bias[i * C_OUT + o0 + r];
        unsigned long long p = pack2(bv, bv);
#pragma unroll
        for (int j = 0; j < 4; ++j) acc[r][j] = p;
    }

    // ---- Prefetch chunk 0 into registers ----
    float4 wreg[8];
    float  xreg[8];
    {
        const float* wp = Wi + tid * C_IN;     // k0 = 0
#pragma unroll
        for (int j = 0; j < 8; ++j)
            wreg[j] = *reinterpret_cast<const float4*>(wp + j * 4);
#pragma unroll
        for (int t = 0; t < 8; ++t) {
            int idx = tid + t * 256;           // idx = k*64 + b
            int k = idx >> 6, b = idx & 63;
            xreg[t] = xi[(size_t)(b * C_IN + k) * N_POS];
        }
    }

    for (int kc = 0; kc < NCHUNK; ++kc) {
        __syncthreads();   // previous chunk's compute done reading smem

        // stage registers -> smem
#pragma unroll
        for (int j = 0; j < 8; ++j) {
            float4 v = wreg[j];
            float* p = &ws[tid * PAD + j * 4];
            p[0] = v.x; p[1] = v.y; p[2] = v.z; p[3] = v.w;
        }
#pragma unroll
        for (int t = 0; t < 8; ++t)
            xs[tid + t * 256] = xreg[t];

        __syncthreads();

        // prefetch next chunk (LDGs overlap with compute below)
        if (kc + 1 < NCHUNK) {
            int k0 = (kc + 1) * KC;
            const float* wp = Wi + tid * C_IN + k0;
#pragma unroll
            for (int j = 0; j < 8; ++j)
                wreg[j] = *reinterpret_cast<const float4*>(wp + j * 4);
#pragma unroll
            for (int t = 0; t < 8; ++t) {
                int idx = tid + t * 256;
                int k = idx >> 6, b = idx & 63;
                xreg[t] = xi[(size_t)(b * C_IN + k0 + k) * N_POS];
            }
        }

        // ---- compute this chunk ----
#pragma unroll 8
        for (int k = 0; k < KC; ++k) {
            unsigned long long xv[4];
#pragma unroll
            for (int j = 0; j < 4; ++j)
                xv[j] = *reinterpret_cast<const unsigned long long*>(
                            &xs[k * BATCH + b0 + 2 * j]);
#pragma unroll
            for (int r = 0; r < 8; ++r) {
                float w = ws[(o0 + r) * PAD + k];
                unsigned long long wv = pack2(w, w);
#pragma unroll
                for (int j = 0; j < 4; ++j)
                    acc[r][j] = ffma2(wv, xv[j], acc[r][j]);
            }
        }
    }

    // ---- epilogue: scatter stores out[b][o][i] ----
#pragma unroll
    for (int r = 0; r < 8; ++r) {
        int o = o0 + r;
#pragma unroll
        for (int j = 0; j < 4; ++j) {
            float v0, v1;
            unpack2(acc[r][j], v0, v1);
            int b = b0 + 2 * j;
            oi[(size_t)(b * C_OUT + o) * N_POS]       = v0;
            oi[(size_t)((b + 1) * C_OUT + o) * N_POS] = v1;
        }
    }
}

extern "C" void kernel_launch(void* const* d_in, const int* in_sizes, int n_in,
                              void* d_out, int out_size) {
    const float* x    = (const float*)d_in[0];
    const float* W    = (const float*)d_in[1];
    const float* bias = (const float*)d_in[2];
    float* out        = (float*)d_out;
    (void)in_sizes; (void)n_in; (void)out_size;

    fclayer_kernel<<<N_POS, 256>>>(x, W, bias, out);
}

// round 3
// speedup vs baseline: 1.6789x; 1.6789x over previous
#include <cuda_runtime.h>
#include <cstdint>

#define NPOS    2048
#define CIN     256
#define COUT    256
#define BATCH   64
#define KC      16            // f32 K elems per chunk
#define NCHUNK  (CIN / KC)    // 16
#define THREADS 256

// ---- per-stage smem byte offsets ----
#define ST_WH       0                    // W hi: 256 rows x 48B (16 bf16 + pad)
#define ST_WL       12288                // W lo
#define ST_XH       24576                // X hi: 64 rows x 48B
#define ST_XL       27648                // X lo
#define STAGE_BYTES 30720
#define SMEM_BYTES  (2 * STAGE_BYTES)    // 61440

#define WSTRIDE 48
#define XSTRIDE 48

static __device__ __forceinline__ uint32_t smem_u32(const void* p) {
    uint32_t a;
    asm("{ .reg .u64 t; cvta.to.shared.u64 t, %1; cvt.u32.u64 %0, t; }"
        : "=r"(a) : "l"(p));
    return a;
}

// pack two f32 -> bf16x2 (a in LOW half, b in HIGH half)
static __device__ __forceinline__ uint32_t cvt_bf16x2(float a, float b) {
    uint32_t r;
    asm("cvt.rn.bf16x2.f32 %0, %1, %2;" : "=r"(r) : "f"(b), "f"(a));
    return r;
}
static __device__ __forceinline__ float lo_as_f32(uint32_t p) { return __uint_as_float(p << 16); }
static __device__ __forceinline__ float hi_as_f32(uint32_t p) { return __uint_as_float(p & 0xffff0000u); }

static __device__ __forceinline__ void sts64(uint32_t addr, uint32_t a, uint32_t b) {
    asm volatile("st.shared.v2.u32 [%0], {%1, %2};" :: "r"(addr), "r"(a), "r"(b) : "memory");
}
static __device__ __forceinline__ void sts16(uint32_t addr, uint32_t v) {
    asm volatile("st.shared.u16 [%0], %1;" :: "r"(addr), "r"(v) : "memory");
}

static __device__ __forceinline__ void ldsm4(uint32_t addr, uint32_t r[4]) {
    asm volatile("ldmatrix.sync.aligned.m8n8.x4.shared.b16 {%0,%1,%2,%3}, [%4];"
                 : "=r"(r[0]), "=r"(r[1]), "=r"(r[2]), "=r"(r[3]) : "r"(addr));
}

static __device__ __forceinline__ void mma16816(float d[4], const uint32_t a[4],
                                                const uint32_t b0, const uint32_t b1) {
    asm volatile(
        "mma.sync.aligned.m16n8k16.row.col.f32.bf16.bf16.f32 "
        "{%0,%1,%2,%3}, {%4,%5,%6,%7}, {%8,%9}, {%0,%1,%2,%3};"
        : "+f"(d[0]), "+f"(d[1]), "+f"(d[2]), "+f"(d[3])
        : "r"(a[0]), "r"(a[1]), "r"(a[2]), "r"(a[3]), "r"(b0), "r"(b1));
}

__global__ __launch_bounds__(THREADS, 2)
void fc_hmma_kernel(const float* __restrict__ x,     // [B, C_IN, N_POS]
                    const float* __restrict__ W,     // [N_POS, C_OUT, C_IN]
                    const float* __restrict__ bias,  // [N_POS, C_OUT]
                    float* __restrict__ out)         // [B, C_OUT, N_POS]
{
    extern __shared__ __align__(128) char smem[];
    const uint32_t sb = smem_u32(smem);

    const int tid  = threadIdx.x;
    const int wid  = tid >> 5;
    const int lane = tid & 31;
    const int i    = blockIdx.x;

    const int wm = wid >> 1;           // 0..3 -> M rows [wm*64, +64)
    const int wn = wid & 1;            // 0..1 -> N cols [wn*32, +32)
    const int m0 = wm * 64;
    const int n0 = wn * 32;

    const float* Wi = W + (size_t)i * (COUT * CIN);
    const float* xi = x + i;

    float acc[4][4][4];
#pragma unroll
    for (int a = 0; a < 4; ++a)
#pragma unroll
        for (int b = 0; b < 4; ++b)
#pragma unroll
            for (int c = 0; c < 4; ++c) acc[a][b][c] = 0.0f;

    // ---- per-chunk load/convert/store helpers (inlined via lambdas) ----
    float4 wraw[4];
    float  xraw[4];

    auto ldg_chunk = [&](int kc) {
#pragma unroll
        for (int t = 0; t < 4; ++t) {
            const int u   = tid + t * THREADS;      // [0,1024)
            const int row = u >> 2;
            const int cq  = u & 3;
            wraw[t] = *reinterpret_cast<const float4*>(Wi + row * CIN + kc * KC + cq * 4);
        }
#pragma unroll
        for (int t = 0; t < 4; ++t) {
            const int u = tid + t * THREADS;        // [0,1024)
            const int k = u & 15;
            const int b = u >> 4;
            xraw[t] = xi[(size_t)(b * CIN + kc * KC + k) * NPOS];
        }
    };

    auto sts_chunk = [&](int buf) {
        const uint32_t stg = sb + buf * STAGE_BYTES;
#pragma unroll
        for (int t = 0; t < 4; ++t) {
            const int u   = tid + t * THREADS;
            const int row = u >> 2;
            const int cq  = u & 3;
            const float4 v = wraw[t];
            const uint32_t h0 = cvt_bf16x2(v.x, v.y);
            const uint32_t h1 = cvt_bf16x2(v.z, v.w);
            const uint32_t g0 = cvt_bf16x2(v.x - lo_as_f32(h0), v.y - hi_as_f32(h0));
            const uint32_t g1 = cvt_bf16x2(v.z - lo_as_f32(h1), v.w - hi_as_f32(h1));
            const uint32_t off = row * WSTRIDE + cq * 8;
            sts64(stg + ST_WH + off, h0, h1);
            sts64(stg + ST_WL + off, g0, g1);
        }
#pragma unroll
        for (int t = 0; t < 4; ++t) {
            const int u = tid + t * THREADS;
            const int k = u & 15;
            const int b = u >> 4;
            const float    f  = xraw[t];
            const uint32_t h  = cvt_bf16x2(f, 0.0f);          // low half = hi(f)
            const float    hf = lo_as_f32(h);
            const uint32_t l  = cvt_bf16x2(f - hf, 0.0f);
            const uint32_t off = b * XSTRIDE + k * 2;
            sts16(stg + ST_XH + off, h);
            sts16(stg + ST_XL + off, l);
        }
    };

    // ---- precomputed ldmatrix lane addresses (offsets within a stage) ----
    // A (W): 16x16 tile at row m: lanes 0-15 -> rows m+(l&15) col 0;
    //        lanes 16-31 -> same rows, col byte 16.
    const uint32_t a_off = (uint32_t)((lane & 15) * WSTRIDE + ((lane >> 4) << 4));
    // B (X): .x4 tiles (n0g+r,0),(n0g+r,16B),(n0g+8+r,0),(n0g+8+r,16B)
    const int bj = lane >> 3, br = lane & 7;
    const uint32_t b_off = (uint32_t)(((bj & 2) * 4 + br) * XSTRIDE + ((bj & 1) << 4));

    auto compute_chunk = [&](int buf) {
        const uint32_t stg = sb + buf * STAGE_BYTES;

        uint32_t bh[2][4], bl[2][4];
#pragma unroll
        for (int ng = 0; ng < 2; ++ng) {
            const uint32_t nb = (uint32_t)((n0 + ng * 16) * XSTRIDE);
            ldsm4(stg + ST_XH + nb + b_off, bh[ng]);
            ldsm4(stg + ST_XL + nb + b_off, bl[ng]);
        }
#pragma unroll
        for (int mt = 0; mt < 4; ++mt) {
            const uint32_t mb = (uint32_t)((m0 + mt * 16) * WSTRIDE);
            uint32_t ah[4], al[4];
            ldsm4(stg + ST_WH + mb + a_off, ah);
            ldsm4(stg + ST_WL + mb + a_off, al);
#pragma unroll
            for (int nt = 0; nt < 4; ++nt) {
                const int ng = nt >> 1, hf = (nt & 1) * 2;
                mma16816(acc[mt][nt], ah, bh[ng][hf], bh[ng][hf + 1]);   // hi*hi
                mma16816(acc[mt][nt], ah, bl[ng][hf], bl[ng][hf + 1]);   // hi*lo
                mma16816(acc[mt][nt], al, bh[ng][hf], bh[ng][hf + 1]);   // lo*hi
            }
        }
    };

    // ---- pipeline: prologue fills stage 0 ----
    ldg_chunk(0);
    sts_chunk(0);
    __syncthreads();

    for (int kc = 0; kc < NCHUNK; ++kc) {
        if (kc + 1 < NCHUNK) ldg_chunk(kc + 1);   // LDGs in flight over compute
        compute_chunk(kc & 1);
        if (kc + 1 < NCHUNK) {
            sts_chunk((kc + 1) & 1);
            __syncthreads();
        }
    }

    // ---- epilogue ----
    const int row0 = lane >> 2;
    const int col0 = (lane & 3) * 2;
    float* oi = out + i;
    const float* bi = bias + (size_t)i * COUT;

#pragma unroll
    for (int mt = 0; mt < 4; ++mt) {
        const int oA = m0 + mt * 16 + row0;
        const int oB = oA + 8;
        const float bvA = bi[oA];
        const float bvB = bi[oB];
#pragma unroll
        for (int nt = 0; nt < 4; ++nt) {
            const int b = n0 + nt * 8 + col0;
            oi[(size_t)(b * COUT + oA) * NPOS]       = acc[mt][nt][0] + bvA;
            oi[(size_t)((b + 1) * COUT + oA) * NPOS] = acc[mt][nt][1] + bvA;
            oi[(size_t)(b * COUT + oB) * NPOS]       = acc[mt][nt][2] + bvB;
            oi[(size_t)((b + 1) * COUT + oB) * NPOS] = acc[mt][nt][3] + bvB;
        }
    }
}

extern "C" void kernel_launch(void* const* d_in, const int* in_sizes, int n_in,
                              void* d_out, int out_size) {
    const float* x    = (const float*)d_in[0];
    const float* W    = (const float*)d_in[1];
    const float* bias = (const float*)d_in[2];
    float* out        = (float*)d_out;
    (void)in_sizes; (void)n_in; (void)out_size;

    cudaFuncSetAttribute(fc_hmma_kernel, cudaFuncAttributeMaxDynamicSharedMemorySize, SMEM_BYTES);
    fc_hmma_kernel<<<NPOS, THREADS, SMEM_BYTES>>>(x, W, bias, out);
}

// round 4
// speedup vs baseline: 2.2455x; 1.3375x over previous
#include <cuda_runtime.h>
#include <cstdint>

#define NPOS    2048
#define CIN     256
#define COUT    256
#define BATCH   64
#define TI      2              // positions per CTA
#define KC      16             // K elems per chunk
#define NCHUNK  (CIN / KC)     // 16
#define THREADS 512

#define XSTRIDE 48             // 32B data + 16B pad (conflict-free ldmatrix)
// per-stage X: [pos][hi/lo] tiles of 64 rows x XSTRIDE
#define XT_BYTES    (BATCH * XSTRIDE)                 // 3072
#define STAGE_BYTES (TI * 2 * XT_BYTES)               // 12288
#define XOFF(s, p, h) ((s) * STAGE_BYTES + (p) * 2 * XT_BYTES + (h) * XT_BYTES)

static __device__ __forceinline__ uint32_t smem_u32(const void* p) {
    uint32_t a;
    asm("{ .reg .u64 t; cvta.to.shared.u64 t, %1; cvt.u32.u64 %0, t; }"
        : "=r"(a) : "l"(p));
    return a;
}

// pack two f32 -> bf16x2 (a -> low half, b -> high half)
static __device__ __forceinline__ uint32_t cvt_bf16x2(float a, float b) {
    uint32_t r;
    asm("cvt.rn.bf16x2.f32 %0, %1, %2;" : "=r"(r) : "f"(b), "f"(a));
    return r;
}
static __device__ __forceinline__ float lo_as_f32(uint32_t p) { return __uint_as_float(p << 16); }
static __device__ __forceinline__ float hi_as_f32(uint32_t p) { return __uint_as_float(p & 0xffff0000u); }

static __device__ __forceinline__ void sts16(uint32_t addr, uint32_t v) {
    asm volatile("st.shared.u16 [%0], %1;" :: "r"(addr), "r"(v) : "memory");
}

static __device__ __forceinline__ void ldsm4(uint32_t addr, uint32_t r[4]) {
    asm volatile("ldmatrix.sync.aligned.m8n8.x4.shared.b16 {%0,%1,%2,%3}, [%4];"
                 : "=r"(r[0]), "=r"(r[1]), "=r"(r[2]), "=r"(r[3]) : "r"(addr));
}

static __device__ __forceinline__ void mma16816(float d[4], const uint32_t a[4],
                                                const uint32_t b0, const uint32_t b1) {
    asm volatile(
        "mma.sync.aligned.m16n8k16.row.col.f32.bf16.bf16.f32 "
        "{%0,%1,%2,%3}, {%4,%5,%6,%7}, {%8,%9}, {%0,%1,%2,%3};"
        : "+f"(d[0]), "+f"(d[1]), "+f"(d[2]), "+f"(d[3])
        : "r"(a[0]), "r"(a[1]), "r"(a[2]), "r"(a[3]), "r"(b0), "r"(b1));
}

__global__ __launch_bounds__(THREADS, 1)
void fc_hmma2_kernel(const float* __restrict__ x,     // [B, C_IN, N_POS]
                     const float* __restrict__ W,     // [N_POS, C_OUT, C_IN]
                     const float* __restrict__ bias,  // [N_POS, C_OUT]
                     float* __restrict__ out)         // [B, C_OUT, N_POS]
{
    __shared__ __align__(128) char xs[2 * STAGE_BYTES];   // 24576 B
    const uint32_t sb = smem_u32(xs);

    const int tid  = threadIdx.x;
    const int wid  = tid >> 5;          // 16 warps, each owns 16 M-rows x both positions
    const int lane = tid & 31;
    const int i0   = blockIdx.x * TI;

    const int row0 = lane >> 2;         // fragment row within 8
    const int k0   = (lane & 3) * 2;    // fragment k pair

    // W pointers for this warp's 16-row slice, both positions
    const float* Wp[TI];
#pragma unroll
    for (int p = 0; p < TI; ++p)
        Wp[p] = W + ((size_t)(i0 + p) * COUT + wid * 16 + row0) * CIN;

    const float* xi = x + i0;

    // accumulators: [pos][ntile(8)][4]
    float acc[TI][8][4];
#pragma unroll
    for (int p = 0; p < TI; ++p)
#pragma unroll
        for (int n = 0; n < 8; ++n)
#pragma unroll
            for (int c = 0; c < 4; ++c) acc[p][n][c] = 0.0f;

    // B-fragment lane address offset (within an X hi/lo tile)
    const int bj = lane >> 3, br = lane & 7;
    const uint32_t b_off = (uint32_t)(((bj & 2) * 4 + br) * XSTRIDE + ((bj & 1) << 4));

    // raw prefetch registers
    float2 wraw[TI][4];    // [pos][ (rr,cc) : a0=(0,0) a1=(8,0) a2=(0,8) a3=(8,8) ]
    float2 xraw[2];

    auto ldg_w = [&](int kc) {
        const int kb = kc * KC + k0;
#pragma unroll
        for (int p = 0; p < TI; ++p) {
            wraw[p][0] = *reinterpret_cast<const float2*>(Wp[p] + kb);
            wraw[p][1] = *reinterpret_cast<const float2*>(Wp[p] + 8 * CIN + kb);
            wraw[p][2] = *reinterpret_cast<const float2*>(Wp[p] + kb + 8);
            wraw[p][3] = *reinterpret_cast<const float2*>(Wp[p] + 8 * CIN + kb + 8);
        }
    };

    auto ldg_x = [&](int kc) {
#pragma unroll
        for (int v = 0; v < 2; ++v) {
            const int u = tid + v * THREADS;      // [0,1024): k = u&15, b = u>>4
            const int k = u & 15, b = u >> 4;
            xraw[v] = *reinterpret_cast<const float2*>(
                xi + (size_t)(b * CIN + kc * KC + k) * NPOS);
        }
    };

    auto sts_x = [&](int s) {
#pragma unroll
        for (int v = 0; v < 2; ++v) {
            const int u = tid + v * THREADS;
            const int k = u & 15, b = u >> 4;
            const float f[2] = {xraw[v].x, xraw[v].y};
#pragma unroll
            for (int p = 0; p < TI; ++p) {
                const uint32_t h  = cvt_bf16x2(f[p], 0.0f);
                const uint32_t l  = cvt_bf16x2(f[p] - lo_as_f32(h), 0.0f);
                const uint32_t off = (uint32_t)(b * XSTRIDE + k * 2);
                sts16(sb + XOFF(s, p, 0) + off, h);
                sts16(sb + XOFF(s, p, 1) + off, l);
            }
        }
    };

    uint32_t ah[TI][4], al[TI][4];
    auto cvt_w = [&]() {
#pragma unroll
        for (int p = 0; p < TI; ++p)
#pragma unroll
            for (int j = 0; j < 4; ++j) {
                const float2 v = wraw[p][j];
                const uint32_t h = cvt_bf16x2(v.x, v.y);
                ah[p][j] = h;
                al[p][j] = cvt_bf16x2(v.x - lo_as_f32(h), v.y - hi_as_f32(h));
            }
    };

    auto compute = [&](int s) {
#pragma unroll
        for (int p = 0; p < TI; ++p) {
            const uint32_t hbase = sb + XOFF(s, p, 0) + b_off;
            const uint32_t lbase = sb + XOFF(s, p, 1) + b_off;
#pragma unroll
            for (int ng = 0; ng < 4; ++ng) {
                uint32_t bh[4], bl[4];
                ldsm4(hbase + (uint32_t)(ng * 16 * XSTRIDE), bh);
                ldsm4(lbase + (uint32_t)(ng * 16 * XSTRIDE), bl);
#pragma unroll
                for (int t = 0; t < 2; ++t) {
                    const int nt = ng * 2 + t;
                    const int hf = t * 2;
                    mma16816(acc[p][nt], ah[p], bh[hf], bh[hf + 1]);   // hi*hi
                    mma16816(acc[p][nt], ah[p], bl[hf], bl[hf + 1]);   // hi*lo
                    mma16816(acc[p][nt], al[p], bh[hf], bh[hf + 1]);   // lo*hi
                }
            }
        }
    };

    // ---- prologue ----
    ldg_w(0);
    ldg_x(0);
    sts_x(0);
    __syncthreads();

    for (int kc = 0; kc < NCHUNK; ++kc) {
        cvt_w();                              // consume wraw before refilling
        if (kc + 1 < NCHUNK) {
            ldg_x(kc + 1);
            ldg_w(kc + 1);
        }
        compute(kc & 1);
        if (kc + 1 < NCHUNK) {
            sts_x((kc + 1) & 1);
            __syncthreads();
        }
    }

    // ---- epilogue: float2 stores along i ----
    float* oi = out + i0;
#pragma unroll
    for (int half = 0; half < 2; ++half) {
        const int o = wid * 16 + row0 + half * 8;
        const float bv0 = bias[(size_t)i0 * COUT + o];
        const float bv1 = bias[(size_t)(i0 + 1) * COUT + o];
#pragma unroll
        for (int nt = 0; nt < 8; ++nt) {
#pragma unroll
            for (int cc = 0; cc < 2; ++cc) {
                const int b = nt * 8 + (lane & 3) * 2 + cc;
                const int c = half * 2 + cc;
                float2 v;
                v.x = acc[0][nt][c] + bv0;
                v.y = acc[1][nt][c] + bv1;
                *reinterpret_cast<float2*>(oi + (size_t)(b * COUT + o) * NPOS) = v;
            }
        }
    }
}

extern "C" void kernel_launch(void* const* d_in, const int* in_sizes, int n_in,
                              void* d_out, int out_size) {
    const float* x    = (const float*)d_in[0];
    const float* W    = (const float*)d_in[1];
    const float* bias = (const float*)d_in[2];
    float* out        = (float*)d_out;
    (void)in_sizes; (void)n_in; (void)out_size;

    fc_hmma2_kernel<<<NPOS / TI, THREADS>>>(x, W, bias, out);
}

// round 5
// speedup vs baseline: 2.6805x; 1.1937x over previous
#include <cuda_runtime.h>
#include <cuda_fp16.h>
#include <cstdint>

#define NPOS    2048
#define CIN     256
#define COUT    256
#define BATCH   64
#define TI      2
#define KC      16
#define NCHUNK  (CIN / KC)     // 16
#define THREADS 512

#define XSTRIDE 48             // 32B data + 16B pad, conflict-free ldmatrix
#define XT_BYTES    (BATCH * XSTRIDE)           // 3072 (one pos, hi only)
#define STAGE_BYTES (TI * XT_BYTES)             // 6144
#define XOFF(s, p) ((s) * STAGE_BYTES + (p) * XT_BYTES)

static __device__ __forceinline__ uint32_t smem_u32(const void* p) {
    uint32_t a;
    asm("{ .reg .u64 t; cvta.to.shared.u64 t, %1; cvt.u32.u64 %0, t; }"
        : "=r"(a) : "l"(p));
    return a;
}

static __device__ __forceinline__ uint32_t h2pack(float lo, float hi) {
    __half2 h = __floats2half2_rn(lo, hi);
    return *reinterpret_cast<uint32_t*>(&h);
}

static __device__ __forceinline__ void sts16(uint32_t addr, uint16_t v) {
    asm volatile("st.shared.u16 [%0], %1;" :: "r"(addr), "h"(v) : "memory");
}

static __device__ __forceinline__ void ldsm4(uint32_t addr, uint32_t r[4]) {
    asm volatile("ldmatrix.sync.aligned.m8n8.x4.shared.b16 {%0,%1,%2,%3}, [%4];"
                 : "=r"(r[0]), "=r"(r[1]), "=r"(r[2]), "=r"(r[3]) : "r"(addr));
}

static __device__ __forceinline__ void mma16816(float d[4], const uint32_t a[4],
                                                const uint32_t b0, const uint32_t b1) {
    asm volatile(
        "mma.sync.aligned.m16n8k16.row.col.f32.f16.f16.f32 "
        "{%0,%1,%2,%3}, {%4,%5,%6,%7}, {%8,%9}, {%0,%1,%2,%3};"
        : "+f"(d[0]), "+f"(d[1]), "+f"(d[2]), "+f"(d[3])
        : "r"(a[0]), "r"(a[1]), "r"(a[2]), "r"(a[3]), "r"(b0), "r"(b1));
}

// k permutation: physical k (within chunk) 4c+d -> smem halfword slot
//   d<2: 2c+d ; d>=2: 2c+d+6   (matches A-frag quad-load assignment)
static __device__ __forceinline__ int kslot(int kappa) {
    const int c = kappa >> 2, d = kappa & 3;
    return (d < 2) ? (2 * c + d) : (2 * c + d + 6);
}

__global__ __launch_bounds__(THREADS, 1)
void fc_hmma3_kernel(const float* __restrict__ x,     // [B, C_IN, N_POS]
                     const float* __restrict__ W,     // [N_POS, C_OUT, C_IN]
                     const float* __restrict__ bias,  // [N_POS, C_OUT]
                     float* __restrict__ out)         // [B, C_OUT, N_POS]
{
    __shared__ __align__(128) char xs[2 * STAGE_BYTES];   // 12288 B
    const uint32_t sb = smem_u32(xs);

    const int tid  = threadIdx.x;
    const int wid  = tid >> 5;          // 16 warps, m16-slice each, both positions
    const int lane = tid & 31;
    const int i0   = blockIdx.x * TI;

    const int row0 = lane >> 2;         // fragment row within 8
    const int kq   = (lane & 3) * 4;    // physical k-quad base for this lane

    // W row pointers (this warp's slice rows row0 / row0+8)
    const float* Wp[TI];
#pragma unroll
    for (int p = 0; p < TI; ++p)
        Wp[p] = W + ((size_t)(i0 + p) * COUT + wid * 16 + row0) * CIN;

    const float* xi = x + i0;

    float acc[TI][8][4];
#pragma unroll
    for (int p = 0; p < TI; ++p)
#pragma unroll
        for (int n = 0; n < 8; ++n)
#pragma unroll
            for (int c = 0; c < 4; ++c) acc[p][n][c] = 0.0f;

    // B-frag ldmatrix lane offset (within a pos-tile)
    const int bj = lane >> 3, br = lane & 7;
    const uint32_t b_off = (uint32_t)(((bj & 2) * 4 + br) * XSTRIDE + ((bj & 1) << 4));

    // raw W prefetch: per pos, rows {row0, row0+8}, 16B quad each
    float4 q[TI][2];
    float2 xraw[2];

    auto ldg_w = [&](int kc) {
        const int kb = kc * KC + kq;
#pragma unroll
        for (int p = 0; p < TI; ++p) {
            q[p][0] = *reinterpret_cast<const float4*>(Wp[p] + kb);
            q[p][1] = *reinterpret_cast<const float4*>(Wp[p] + 8 * CIN + kb);
        }
    };

    auto ldg_x = [&](int kc) {
#pragma unroll
        for (int v = 0; v < 2; ++v) {
            const int u = tid + v * THREADS;      // [0,1024): kappa=u&15, b=u>>4
            const int k = u & 15, b = u >> 4;
            xraw[v] = *reinterpret_cast<const float2*>(
                xi + (size_t)(b * CIN + kc * KC + k) * NPOS);
        }
    };

    auto sts_x = [&](int s) {
#pragma unroll
        for (int v = 0; v < 2; ++v) {
            const int u = tid + v * THREADS;
            const int k = u & 15, b = u >> 4;
            const uint32_t off = (uint32_t)(b * XSTRIDE + kslot(k) * 2);
            const float f[2] = {xraw[v].x, xraw[v].y};
#pragma unroll
            for (int p = 0; p < TI; ++p) {
                const __half h = __float2half_rn(f[p]);
                sts16(sb + XOFF(s, p) + off, *reinterpret_cast<const uint16_t*>(&h));
            }
        }
    };

    // converted A fragments (hi / lo)
    uint32_t ah[TI][4], al[TI][4];
    auto cvt_w = [&]() {
#pragma unroll
        for (int p = 0; p < TI; ++p) {
#pragma unroll
            for (int r = 0; r < 2; ++r) {         // r=0 -> a0/a2, r=1 -> a1/a3
                const float4 v = q[p][r];
                const uint32_t h02 = h2pack(v.x, v.y);   // phys k {4c, 4c+1}
                const uint32_t h13 = h2pack(v.z, v.w);   // phys k {4c+2, 4c+3}
                __half2 hh02 = *reinterpret_cast<const __half2*>(&h02);
                __half2 hh13 = *reinterpret_cast<const __half2*>(&h13);
                ah[p][r]     = h02;                       // a0 / a1
                ah[p][r + 2] = h13;                       // a2 / a3
                al[p][r]     = h2pack(v.x - __low2float(hh02), v.y - __high2float(hh02));
                al[p][r + 2] = h2pack(v.z - __low2float(hh13), v.w - __high2float(hh13));
            }
        }
    };

    auto compute = [&](int s) {
#pragma unroll
        for (int p = 0; p < TI; ++p) {
            const uint32_t hbase = sb + XOFF(s, p) + b_off;
            uint32_t bh[16];
#pragma unroll
            for (int ng = 0; ng < 4; ++ng)
                ldsm4(hbase + (uint32_t)(ng * 16 * XSTRIDE), bh + 4 * ng);
#pragma unroll
            for (int nt = 0; nt < 8; ++nt) {
                const int ng = nt >> 1, t = nt & 1;
                const uint32_t b0 = bh[ng * 4 + t * 2];
                const uint32_t b1 = bh[ng * 4 + t * 2 + 1];
                mma16816(acc[p][nt], ah[p], b0, b1);   // whi * xh
                mma16816(acc[p][nt], al[p], b0, b1);   // wlo * xh
            }
        }
    };

    // ---- prologue ----
    ldg_w(0);
    ldg_x(0);
    sts_x(0);
    __syncthreads();

    for (int kc = 0; kc < NCHUNK; ++kc) {
        cvt_w();                              // consume q before refilling
        if (kc + 1 < NCHUNK) {
            ldg_x(kc + 1);
            ldg_w(kc + 1);
        }
        compute(kc & 1);
        if (kc + 1 < NCHUNK) {
            sts_x((kc + 1) & 1);
            __syncthreads();
        }
    }

    // ---- epilogue: float2 stores along i ----
    float* oi = out + i0;
#pragma unroll
    for (int half = 0; half < 2; ++half) {
        const int o = wid * 16 + row0 + half * 8;
        const float bv0 = bias[(size_t)i0 * COUT + o];
        const float bv1 = bias[(size_t)(i0 + 1) * COUT + o];
#pragma unroll
        for (int nt = 0; nt < 8; ++nt) {
#pragma unroll
            for (int cc = 0; cc < 2; ++cc) {
                const int b = nt * 8 + (lane & 3) * 2 + cc;
                const int c = half * 2 + cc;
                float2 v;
                v.x = acc[0][nt][c] + bv0;
                v.y = acc[1][nt][c] + bv1;
                *reinterpret_cast<float2*>(oi + (size_t)(b * COUT + o) * NPOS) = v;
            }
        }
    }
}

extern "C" void kernel_launch(void* const* d_in, const int* in_sizes, int n_in,
                              void* d_out, int out_size) {
    const float* x    = (const float*)d_in[0];
    const float* W    = (const float*)d_in[1];
    const float* bias = (const float*)d_in[2];
    float* out        = (float*)d_out;
    (void)in_sizes; (void)n_in; (void)out_size;

    fc_hmma3_kernel<<<NPOS / TI, THREADS>>>(x, W, bias, out);
}

// round 6
// speedup vs baseline: 3.0543x; 1.1394x over previous
#include <cuda_runtime.h>
#include <cuda_fp16.h>
#include <cstdint>

#define NPOS    2048
#define CIN     256
#define COUT    256
#define BATCH   64
#define TI      2
#define KC      16
#define NCHUNK  (CIN / KC)     // 16
#define THREADS 512
#define NSTAGE  4

#define XSTRIDE 48             // 32B data + 16B pad, conflict-free ldmatrix
#define XT_BYTES    (BATCH * XSTRIDE)           // 3072 (one pos)
#define STAGE_BYTES (TI * XT_BYTES)             // 6144
#define XOFF(s, p) ((s) * STAGE_BYTES + (p) * XT_BYTES)

static __device__ __forceinline__ uint32_t smem_u32(const void* p) {
    uint32_t a;
    asm("{ .reg .u64 t; cvta.to.shared.u64 t, %1; cvt.u32.u64 %0, t; }"
        : "=r"(a) : "l"(p));
    return a;
}

static __device__ __forceinline__ uint32_t h2pack(float lo, float hi) {
    __half2 h = __floats2half2_rn(lo, hi);
    return *reinterpret_cast<uint32_t*>(&h);
}

static __device__ __forceinline__ void sts16(uint32_t addr, uint16_t v) {
    asm volatile("st.shared.u16 [%0], %1;" :: "r"(addr), "h"(v) : "memory");
}

static __device__ __forceinline__ void ldsm4(uint32_t addr, uint32_t r[4]) {
    asm volatile("ldmatrix.sync.aligned.m8n8.x4.shared.b16 {%0,%1,%2,%3}, [%4];"
                 : "=r"(r[0]), "=r"(r[1]), "=r"(r[2]), "=r"(r[3]) : "r"(addr));
}

static __device__ __forceinline__ void mma16816(float d[4], const uint32_t a[4],
                                                const uint32_t b0, const uint32_t b1) {
    asm volatile(
        "mma.sync.aligned.m16n8k16.row.col.f32.f16.f16.f32 "
        "{%0,%1,%2,%3}, {%4,%5,%6,%7}, {%8,%9}, {%0,%1,%2,%3};"
        : "+f"(d[0]), "+f"(d[1]), "+f"(d[2]), "+f"(d[3])
        : "r"(a[0]), "r"(a[1]), "r"(a[2]), "r"(a[3]), "r"(b0), "r"(b1));
}

// k permutation: physical k (within chunk) 4c+d -> smem halfword slot
//   d<2: 2c+d ; d>=2: 2c+d+6   (matches A-frag quad-load assignment)
static __device__ __forceinline__ int kslot(int kappa) {
    const int c = kappa >> 2, d = kappa & 3;
    return (d < 2) ? (2 * c + d) : (2 * c + d + 6);
}

__global__ __launch_bounds__(THREADS, 1)
void fc_hmma4_kernel(const float* __restrict__ x,     // [B, C_IN, N_POS]
                     const float* __restrict__ W,     // [N_POS, C_OUT, C_IN]
                     const float* __restrict__ bias,  // [N_POS, C_OUT]
                     float* __restrict__ out)         // [B, C_OUT, N_POS]
{
    __shared__ __align__(128) char xs[NSTAGE * STAGE_BYTES];   // 24576 B
    const uint32_t sb = smem_u32(xs);

    const int tid  = threadIdx.x;
    const int wid  = tid >> 5;          // 16 warps, m16-slice each, both positions
    const int lane = tid & 31;
    const int i0   = blockIdx.x * TI;

    const int row0 = lane >> 2;
    const int kq   = (lane & 3) * 4;    // physical k-quad base

    const float* Wp[TI];
#pragma unroll
    for (int p = 0; p < TI; ++p)
        Wp[p] = W + ((size_t)(i0 + p) * COUT + wid * 16 + row0) * CIN;

    const float* xi = x + i0;

    float acc[TI][8][4];
#pragma unroll
    for (int p = 0; p < TI; ++p)
#pragma unroll
        for (int n = 0; n < 8; ++n)
#pragma unroll
            for (int c = 0; c < 4; ++c) acc[p][n][c] = 0.0f;

    const int bj = lane >> 3, br = lane & 7;
    const uint32_t b_off = (uint32_t)(((bj & 2) * 4 + br) * XSTRIDE + ((bj & 1) << 4));

    // prefetch registers
    float4 q[TI][2];        // W quads, depth 1
    float2 xr[2][2];        // x, depth 2 (two chunk sets)

    // precomputed x addresses for this thread's two (b,k) units
    const float* xaddr[2];
    int xslot[2];
#pragma unroll
    for (int v = 0; v < 2; ++v) {
        const int u = tid + v * THREADS;      // [0,1024): kappa=u&15, b=u>>4
        const int k = u & 15, b = u >> 4;
        xaddr[v] = xi + (size_t)(b * CIN + k) * NPOS;
        xslot[v] = b * XSTRIDE + kslot(k) * 2;
    }

    auto ldg_w = [&](int kc) {
        const int kb = kc * KC + kq;
#pragma unroll
        for (int p = 0; p < TI; ++p) {
            q[p][0] = *reinterpret_cast<const float4*>(Wp[p] + kb);
            q[p][1] = *reinterpret_cast<const float4*>(Wp[p] + 8 * CIN + kb);
        }
    };

    auto ldg_x = [&](int kc, int set) {
#pragma unroll
        for (int v = 0; v < 2; ++v)
            xr[set][v] = *reinterpret_cast<const float2*>(xaddr[v] + (size_t)kc * KC * NPOS);
    };

    auto sts_x = [&](int s, int set) {
#pragma unroll
        for (int v = 0; v < 2; ++v) {
            const float f[2] = {xr[set][v].x, xr[set][v].y};
#pragma unroll
            for (int p = 0; p < TI; ++p) {
                const __half h = __float2half_rn(f[p]);
                sts16(sb + XOFF(s, p) + (uint32_t)xslot[v],
                      *reinterpret_cast<const uint16_t*>(&h));
            }
        }
    };

    uint32_t ah[TI][4], al[TI][4];
    auto cvt_w = [&]() {
#pragma unroll
        for (int p = 0; p < TI; ++p) {
#pragma unroll
            for (int r = 0; r < 2; ++r) {
                const float4 v = q[p][r];
                const uint32_t h02 = h2pack(v.x, v.y);
                const uint32_t h13 = h2pack(v.z, v.w);
                __half2 hh02 = *reinterpret_cast<const __half2*>(&h02);
                __half2 hh13 = *reinterpret_cast<const __half2*>(&h13);
                ah[p][r]     = h02;
                ah[p][r + 2] = h13;
                al[p][r]     = h2pack(v.x - __low2float(hh02), v.y - __high2float(hh02));
                al[p][r + 2] = h2pack(v.z - __low2float(hh13), v.w - __high2float(hh13));
            }
        }
    };

    auto compute = [&](int s) {
#pragma unroll
        for (int p = 0; p < TI; ++p) {
            const uint32_t hbase = sb + XOFF(s, p) + b_off;
            uint32_t bh[16];
#pragma unroll
            for (int ng = 0; ng < 4; ++ng)
                ldsm4(hbase + (uint32_t)(ng * 16 * XSTRIDE), bh + 4 * ng);
#pragma unroll
            for (int nt = 0; nt < 8; ++nt) {
                const int ng = nt >> 1, t = nt & 1;
                const uint32_t b0 = bh[ng * 4 + t * 2];
                const uint32_t b1 = bh[ng * 4 + t * 2 + 1];
                mma16816(acc[p][nt], ah[p], b0, b1);
                mma16816(acc[p][nt], al[p], b0, b1);
            }
        }
    };

    // ---- prologue: fill stage 0, prefetch chunk 1 ----
    ldg_w(0);
    ldg_x(0, 0);
    ldg_x(1, 1);
    sts_x(0, 0);
    __syncthreads();

    for (int kc = 0; kc < NCHUNK; ++kc) {
        cvt_w();                                      // consume q(kc)
        if (kc + 1 < NCHUNK) {
            ldg_w(kc + 1);                            // refill q
            sts_x((kc + 1) & (NSTAGE - 1), (kc + 1) & 1);   // stage kc+1 from set
        }
        if (kc + 2 < NCHUNK)
            ldg_x(kc + 2, kc & 1);                    // refill freed set
        compute(kc & (NSTAGE - 1));
        if (kc + 1 < NCHUNK)
            __syncthreads();
    }

    // ---- epilogue: float2 stores along i ----
    float* oi = out + i0;
#pragma unroll
    for (int half = 0; half < 2; ++half) {
        const int o = wid * 16 + row0 + half * 8;
        const float bv0 = bias[(size_t)i0 * COUT + o];
        const float bv1 = bias[(size_t)(i0 + 1) * COUT + o];
#pragma unroll
        for (int nt = 0; nt < 8; ++nt) {
#pragma unroll
            for (int cc = 0; cc < 2; ++cc) {
                const int b = nt * 8 + (lane & 3) * 2 + cc;
                const int c = half * 2 + cc;
                float2 v;
                v.x = acc[0][nt][c] + bv0;
                v.y = acc[1][nt][c] + bv1;
                *reinterpret_cast<float2*>(oi + (size_t)(b * COUT + o) * NPOS) = v;
            }
        }
    }
}

extern "C" void kernel_launch(void* const* d_in, const int* in_sizes, int n_in,
                              void* d_out, int out_size) {
    const float* x    = (const float*)d_in[0];
    const float* W    = (const float*)d_in[1];
    const float* bias = (const float*)d_in[2];
    float* out        = (float*)d_out;
    (void)in_sizes; (void)n_in; (void)out_size;

    fc_hmma4_kernel<<<NPOS / TI, THREADS>>>(x, W, bias, out);
}